// round 13
// baseline (speedup 1.0000x reference)
#include <cuda_runtime.h>

#define NN    100000
#define EDGES 3200000
#define INC   128
#define HID   16
#define OUTC  64
#define NBLK  ((NN + 1023) / 1024)   // 98
#define G1BLK (NN / 16)              // 6250 gemm1 blocks
#define SCBLK ((EDGES + 255) / 256)  // 12500 scatter blocks

// Scratch (allocation-free rule: __device__ globals)
__device__ __align__(16) int    g_deg_i[NN];
__device__ __align__(16) float  g_dinv[NN];
__device__ __align__(16) int    g_off[NN + 1];
__device__ __align__(16) int    g_cur[NN];
__device__ __align__(16) float2 g_srcw[EDGES];   // {src_as_float_bits, dinv[src]}
__device__ __align__(16) int    g_bsum[NBLK];
__device__ __align__(16) int    g_boff[NBLK];
__device__ __align__(16) float  g_h[NN * HID];   // gemm1 out
__device__ __align__(16) float  g_h2[NN * HID];  // relu(agg1+b1)
__device__ __align__(16) float  g_agg[NN * HID]; // agg2

__global__ void k_init_deg() {
    int i = blockIdx.x * blockDim.x + threadIdx.x;
    if (i < NN) g_deg_i[i] = 1;  // self loop contributes 1
}

__global__ void k_count(const int* __restrict__ col, int E) {
    int i = blockIdx.x * blockDim.x + threadIdx.x;
    int e0 = i * 4;
    if (e0 + 3 < E) {
        int4 c4 = ((const int4*)col)[i];
        atomicAdd(&g_deg_i[c4.x], 1);
        atomicAdd(&g_deg_i[c4.y], 1);
        atomicAdd(&g_deg_i[c4.z], 1);
        atomicAdd(&g_deg_i[c4.w], 1);
    } else {
        for (int e = e0; e < E; e++) atomicAdd(&g_deg_i[col[e]], 1);
    }
}

// dinv + per-block degree sum fused (both are one pass over g_deg_i).
__global__ void k_dinv_blocksum() {
    __shared__ int sh[1024];
    int t = threadIdx.x;
    int i = blockIdx.x * 1024 + t;
    int d = (i < NN) ? g_deg_i[i] : 1;
    if (i < NN) g_dinv[i] = rsqrtf((float)d);
    sh[t] = (i < NN) ? d - 1 : 0;
    __syncthreads();
    for (int o = 512; o > 0; o >>= 1) {
        if (t < o) sh[t] += sh[t + o];
        __syncthreads();
    }
    if (t == 0) g_bsum[blockIdx.x] = sh[0];
}

__global__ void k_bscan() {  // 1 block, 128 threads >= NBLK
    __shared__ int sh[128];
    int t = threadIdx.x;
    int v = (t < NBLK) ? g_bsum[t] : 0;
    sh[t] = v;
    __syncthreads();
    for (int o = 1; o < 128; o <<= 1) {
        int u = (t >= o) ? sh[t - o] : 0;
        __syncthreads();
        sh[t] += u;
        __syncthreads();
    }
    if (t < NBLK) g_boff[t] = sh[t] - v;  // exclusive
}

__global__ void k_off() {
    __shared__ int sh[1024];
    int t = threadIdx.x;
    int i = blockIdx.x * 1024 + t;
    int v = (i < NN) ? g_deg_i[i] - 1 : 0;
    sh[t] = v;
    __syncthreads();
    for (int o = 1; o < 1024; o <<= 1) {  // inclusive Hillis-Steele
        int u = (t >= o) ? sh[t - o] : 0;
        __syncthreads();
        sh[t] += u;
        __syncthreads();
    }
    int excl = sh[t] - v + g_boff[blockIdx.x];
    if (i < NN) {
        g_off[i] = excl;
        g_cur[i] = excl;
        if (i == NN - 1) g_off[NN] = excl + v;
    }
}

// Fused: blocks [0, G1BLK) do gemm1 (h = X @ W1); blocks [G1BLK, ...) scatter
// edges into CSR. Independent work, different resource mixes -> overlap.
__global__ void k_gemm1_scatter(const float* __restrict__ x,
                                const float* __restrict__ W1,
                                const int* __restrict__ row,
                                const int* __restrict__ col, int E) {
    __shared__ float4 xs[16 * 32];    // 16 rows x 32 float4 (K=128)
    __shared__ float4 wsT[16 * 33];   // 16 cols x 32 float4, stride 33 (pad)
    int t = threadIdx.x;
    if (blockIdx.x < G1BLK) {
        int r0 = blockIdx.x * 16;
        const float4* xg = (const float4*)x;
        for (int i = t; i < 512; i += 256)
            xs[i] = xg[r0 * 32 + i];
        for (int i = t; i < 512; i += 256) {
            int c = i >> 5, k4 = i & 31;
            float4 w;
            w.x = W1[(k4 * 4 + 0) * 16 + c];
            w.y = W1[(k4 * 4 + 1) * 16 + c];
            w.z = W1[(k4 * 4 + 2) * 16 + c];
            w.w = W1[(k4 * 4 + 3) * 16 + c];
            wsT[c * 33 + k4] = w;
        }
        __syncthreads();
        int r = t >> 4, c = t & 15;
        float acc = 0.0f;
#pragma unroll
        for (int k4 = 0; k4 < 32; k4++) {
            float4 xv = xs[r * 32 + k4];
            float4 wv = wsT[c * 33 + k4];
            acc = fmaf(xv.x, wv.x, acc);
            acc = fmaf(xv.y, wv.y, acc);
            acc = fmaf(xv.z, wv.z, acc);
            acc = fmaf(xv.w, wv.w, acc);
        }
        g_h[(r0 + r) * HID + c] = acc;
    } else {
        int e = (blockIdx.x - G1BLK) * 256 + t;
        if (e >= E) return;
        int r = row[e];
        int p = atomicAdd(&g_cur[col[e]], 1);
        float2 v; v.x = __int_as_float(r); v.y = g_dinv[r];
        g_srcw[p] = v;
    }
}

__device__ __forceinline__ void fma4(float4& a, float4 v, float w) {
    a.x = fmaf(v.x, w, a.x); a.y = fmaf(v.y, w, a.y);
    a.z = fmaf(v.z, w, a.z); a.w = fmaf(v.w, w, a.w);
}

// Pull-mode aggregation, 4 threads/node, thread j owns cols [4j,4j+4).
// 8-edge unroll: 8 random 16B gathers in flight (MLP=8).
// RELU=true: out = relu(acc + b1) (layer-1 epilogue fused).
template <bool RELU>
__global__ void __launch_bounds__(256) k_pull(const float* __restrict__ src,
                                              float* __restrict__ dst,
                                              const float* __restrict__ b1) {
    unsigned gid = blockIdx.x * blockDim.x + threadIdx.x;
    int n = gid >> 2;
    int j = gid & 3;
    if (n >= NN) return;
    float din = g_dinv[n];
    const float4* H = (const float4*)src;
    float4 acc = H[n * 4 + j];
    float w0 = din * din;
    acc.x *= w0; acc.y *= w0; acc.z *= w0; acc.w *= w0;
    int e = g_off[n], eend = g_off[n + 1];
    for (; e + 7 < eend; e += 8) {
        float2 p0 = g_srcw[e + 0], p1 = g_srcw[e + 1];
        float2 p2 = g_srcw[e + 2], p3 = g_srcw[e + 3];
        float2 p4 = g_srcw[e + 4], p5 = g_srcw[e + 5];
        float2 p6 = g_srcw[e + 6], p7 = g_srcw[e + 7];
        float4 v0 = H[__float_as_int(p0.x) * 4 + j];
        float4 v1 = H[__float_as_int(p1.x) * 4 + j];
        float4 v2 = H[__float_as_int(p2.x) * 4 + j];
        float4 v3 = H[__float_as_int(p3.x) * 4 + j];
        float4 v4 = H[__float_as_int(p4.x) * 4 + j];
        float4 v5 = H[__float_as_int(p5.x) * 4 + j];
        float4 v6 = H[__float_as_int(p6.x) * 4 + j];
        float4 v7 = H[__float_as_int(p7.x) * 4 + j];
        fma4(acc, v0, p0.y * din);
        fma4(acc, v1, p1.y * din);
        fma4(acc, v2, p2.y * din);
        fma4(acc, v3, p3.y * din);
        fma4(acc, v4, p4.y * din);
        fma4(acc, v5, p5.y * din);
        fma4(acc, v6, p6.y * din);
        fma4(acc, v7, p7.y * din);
    }
    for (; e < eend; e++) {
        float2 p = g_srcw[e];
        fma4(acc, H[__float_as_int(p.x) * 4 + j], p.y * din);
    }
    if (RELU) {
        float4 b = ((const float4*)b1)[j];
        acc.x = fmaxf(acc.x + b.x, 0.0f);
        acc.y = fmaxf(acc.y + b.y, 0.0f);
        acc.z = fmaxf(acc.z + b.z, 0.0f);
        acc.w = fmaxf(acc.w + b.w, 0.0f);
    }
    ((float4*)dst)[n * 4 + j] = acc;
}

// out = g_agg @ W2 + b2. 4 rows per 256-thread block.
__global__ void k_gemm2(const float* __restrict__ W2, const float* __restrict__ b2,
                        float* __restrict__ out) {
    __shared__ float as[4 * 16];
    __shared__ float ws[16 * 64];
    int r0 = blockIdx.x * 4;
    int t = threadIdx.x;
    if (t < 64) as[t] = g_agg[r0 * HID + t];
    for (int i = t; i < 16 * 64; i += 256) ws[i] = W2[i];
    __syncthreads();
    int r = t >> 6, c = t & 63;
    float acc = b2[c];
#pragma unroll
    for (int k = 0; k < 16; k++)
        acc = fmaf(as[r * 16 + k], ws[k * 64 + c], acc);
    out[(r0 + r) * OUTC + c] = acc;
}

extern "C" void kernel_launch(void* const* d_in, const int* in_sizes, int n_in,
                              void* d_out, int out_size) {
    const float* x   = (const float*)d_in[0];
    const int*   ei  = (const int*)d_in[1];   // JAX silently downcast int64->int32
    const float* W1  = (const float*)d_in[2];
    const float* b1  = (const float*)d_in[3];
    const float* W2  = (const float*)d_in[4];
    const float* b2  = (const float*)d_in[5];
    float*       out = (float*)d_out;

    int E = in_sizes[1] / 2;
    const int* row = ei;       // sources
    const int* col = ei + E;   // targets

    float* p_h;   cudaGetSymbolAddress((void**)&p_h,   g_h);
    float* p_h2;  cudaGetSymbolAddress((void**)&p_h2,  g_h2);
    float* p_agg; cudaGetSymbolAddress((void**)&p_agg, g_agg);

    k_init_deg<<<(NN + 255) / 256, 256>>>();
    k_count<<<(E / 4 + 255) / 256, 256>>>(col, E);
    k_dinv_blocksum<<<NBLK, 1024>>>();
    k_bscan<<<1, 128>>>();
    k_off<<<NBLK, 1024>>>();
    k_gemm1_scatter<<<G1BLK + (E + 255) / 256, 256>>>(x, W1, row, col, E);
    k_pull<true><<<(NN * 4 + 255) / 256, 256>>>(p_h, p_h2, b1);
    k_pull<false><<<(NN * 4 + 255) / 256, 256>>>(p_h2, p_agg, b1);
    k_gemm2<<<NN / 4, 256>>>(W2, b2, out);
}

// round 14
// speedup vs baseline: 1.0540x; 1.0540x over previous
#include <cuda_runtime.h>

#define NN    100000
#define EDGES 3200000
#define INC   128
#define HID   16
#define OUTC  64
#define NBLK  ((NN + 1023) / 1024)   // 98

// Scratch (allocation-free rule: __device__ globals)
__device__ __align__(16) int    g_deg_i[NN];
__device__ __align__(16) float  g_dinv[NN];
__device__ __align__(16) int    g_off[NN + 1];
__device__ __align__(16) int    g_cur[NN];
__device__ __align__(16) int    g_srcI[EDGES];   // CSR: src index only (4B)
__device__ __align__(16) int    g_bsum[NBLK];
__device__ __align__(16) int    g_boff[NBLK];
__device__ __align__(16) float  g_h[NN * HID];   // h1 * dinv (pre-scaled)
__device__ __align__(16) float  g_h2[NN * HID];  // relu(agg1+b1) * dinv
__device__ __align__(16) float  g_agg[NN * HID]; // agg2

__global__ void k_init_deg() {
    int i = blockIdx.x * blockDim.x + threadIdx.x;
    if (i < NN) g_deg_i[i] = 1;  // self loop contributes 1
}

__global__ void k_count(const int* __restrict__ col, int E) {
    int i = blockIdx.x * blockDim.x + threadIdx.x;
    int e0 = i * 4;
    if (e0 + 3 < E) {
        int4 c4 = ((const int4*)col)[i];
        atomicAdd(&g_deg_i[c4.x], 1);
        atomicAdd(&g_deg_i[c4.y], 1);
        atomicAdd(&g_deg_i[c4.z], 1);
        atomicAdd(&g_deg_i[c4.w], 1);
    } else {
        for (int e = e0; e < E; e++) atomicAdd(&g_deg_i[col[e]], 1);
    }
}

// dinv + per-block degree sum fused (both are one pass over g_deg_i).
__global__ void k_dinv_blocksum() {
    __shared__ int sh[1024];
    int t = threadIdx.x;
    int i = blockIdx.x * 1024 + t;
    int d = (i < NN) ? g_deg_i[i] : 1;
    if (i < NN) g_dinv[i] = rsqrtf((float)d);
    sh[t] = (i < NN) ? d - 1 : 0;
    __syncthreads();
    for (int o = 512; o > 0; o >>= 1) {
        if (t < o) sh[t] += sh[t + o];
        __syncthreads();
    }
    if (t == 0) g_bsum[blockIdx.x] = sh[0];
}

__global__ void k_bscan() {  // 1 block, 128 threads >= NBLK
    __shared__ int sh[128];
    int t = threadIdx.x;
    int v = (t < NBLK) ? g_bsum[t] : 0;
    sh[t] = v;
    __syncthreads();
    for (int o = 1; o < 128; o <<= 1) {
        int u = (t >= o) ? sh[t - o] : 0;
        __syncthreads();
        sh[t] += u;
        __syncthreads();
    }
    if (t < NBLK) g_boff[t] = sh[t] - v;  // exclusive
}

__global__ void k_off() {
    __shared__ int sh[1024];
    int t = threadIdx.x;
    int i = blockIdx.x * 1024 + t;
    int v = (i < NN) ? g_deg_i[i] - 1 : 0;
    sh[t] = v;
    __syncthreads();
    for (int o = 1; o < 1024; o <<= 1) {  // inclusive Hillis-Steele
        int u = (t >= o) ? sh[t - o] : 0;
        __syncthreads();
        sh[t] += u;
        __syncthreads();
    }
    int excl = sh[t] - v + g_boff[blockIdx.x];
    if (i < NN) {
        g_off[i] = excl;
        g_cur[i] = excl;
        if (i == NN - 1) g_off[NN] = excl + v;
    }
}

__global__ void k_scatter(const int* __restrict__ row,
                          const int* __restrict__ col, int E) {
    int e = blockIdx.x * blockDim.x + threadIdx.x;
    if (e >= E) return;
    int p = atomicAdd(&g_cur[col[e]], 1);
    g_srcI[p] = row[e];
}

// h' = (X @ W1) * dinv[node]. 16 rows / 256-thread block.
__global__ void k_gemm1(const float* __restrict__ x, const float* __restrict__ W1) {
    __shared__ float4 xs[16 * 32];    // 16 rows x 32 float4 (K=128)
    __shared__ float4 wsT[16 * 33];   // 16 cols x 32 float4, stride 33 (pad)
    int r0 = blockIdx.x * 16;
    int t = threadIdx.x;
    const float4* xg = (const float4*)x;
    for (int i = t; i < 512; i += 256)
        xs[i] = xg[r0 * 32 + i];
    for (int i = t; i < 512; i += 256) {
        int c = i >> 5, k4 = i & 31;
        float4 w;
        w.x = W1[(k4 * 4 + 0) * 16 + c];
        w.y = W1[(k4 * 4 + 1) * 16 + c];
        w.z = W1[(k4 * 4 + 2) * 16 + c];
        w.w = W1[(k4 * 4 + 3) * 16 + c];
        wsT[c * 33 + k4] = w;
    }
    __syncthreads();
    int r = t >> 4, c = t & 15;
    float acc = 0.0f;
#pragma unroll
    for (int k4 = 0; k4 < 32; k4++) {
        float4 xv = xs[r * 32 + k4];
        float4 wv = wsT[c * 33 + k4];
        acc = fmaf(xv.x, wv.x, acc);
        acc = fmaf(xv.y, wv.y, acc);
        acc = fmaf(xv.z, wv.z, acc);
        acc = fmaf(xv.w, wv.w, acc);
    }
    g_h[(r0 + r) * HID + c] = acc * g_dinv[r0 + r];  // pre-scale by dinv
}

// Warp-per-node pull. Input pre-scaled: H'[s] = h[s]*dinv[s].
// out = din * (H'[n] + sum_s H'[s]); RELU epilogue also re-scales by din.
// Lane = sub*4 + j: quad j covers cols [4j,4j+4), sub enumerates 8 edges/iter.
template <bool RELU>
__global__ void __launch_bounds__(256) k_pullw(const float4* __restrict__ Hp,
                                               float4* __restrict__ dst,
                                               const float* __restrict__ b1) {
    int warp = (blockIdx.x * blockDim.x + threadIdx.x) >> 5;
    if (warp >= NN) return;
    int lane = threadIdx.x & 31;
    int sub = lane >> 2, j = lane & 3;
    int n = warp;
    float din = g_dinv[n];
    float4 acc = make_float4(0.f, 0.f, 0.f, 0.f);
    if (sub == 0) acc = Hp[n * 4 + j];  // self loop (H'[n], scaled by din at end)
    int e = g_off[n] + sub;
    int eend = g_off[n + 1];
    // 32 edges per warp-iteration (4 per lane, stride 8)
    for (; e + 24 < eend; e += 32) {
        int s0 = g_srcI[e +  0], s1 = g_srcI[e +  8];
        int s2 = g_srcI[e + 16], s3 = g_srcI[e + 24];
        float4 v0 = Hp[s0 * 4 + j], v1 = Hp[s1 * 4 + j];
        float4 v2 = Hp[s2 * 4 + j], v3 = Hp[s3 * 4 + j];
        acc.x += (v0.x + v1.x) + (v2.x + v3.x);
        acc.y += (v0.y + v1.y) + (v2.y + v3.y);
        acc.z += (v0.z + v1.z) + (v2.z + v3.z);
        acc.w += (v0.w + v1.w) + (v2.w + v3.w);
    }
    for (; e < eend; e += 8) {
        float4 v = Hp[g_srcI[e] * 4 + j];
        acc.x += v.x; acc.y += v.y; acc.z += v.z; acc.w += v.w;
    }
    // reduce the 8 sub-accumulators (same j) via butterfly
#pragma unroll
    for (int o = 4; o < 32; o <<= 1) {
        acc.x += __shfl_xor_sync(0xffffffffu, acc.x, o);
        acc.y += __shfl_xor_sync(0xffffffffu, acc.y, o);
        acc.z += __shfl_xor_sync(0xffffffffu, acc.z, o);
        acc.w += __shfl_xor_sync(0xffffffffu, acc.w, o);
    }
    if (sub == 0) {
        float4 r;
        if (RELU) {
            float4 b = ((const float4*)b1)[j];
            r.x = fmaxf(din * acc.x + b.x, 0.f) * din;
            r.y = fmaxf(din * acc.y + b.y, 0.f) * din;
            r.z = fmaxf(din * acc.z + b.z, 0.f) * din;
            r.w = fmaxf(din * acc.w + b.w, 0.f) * din;
        } else {
            r.x = din * acc.x; r.y = din * acc.y;
            r.z = din * acc.z; r.w = din * acc.w;
        }
        dst[n * 4 + j] = r;
    }
}

// out = g_agg @ W2 + b2. 4 rows per 256-thread block.
__global__ void k_gemm2(const float* __restrict__ W2, const float* __restrict__ b2,
                        float* __restrict__ out) {
    __shared__ float as[4 * 16];
    __shared__ float ws[16 * 64];
    int r0 = blockIdx.x * 4;
    int t = threadIdx.x;
    if (t < 64) as[t] = g_agg[r0 * HID + t];
    for (int i = t; i < 16 * 64; i += 256) ws[i] = W2[i];
    __syncthreads();
    int r = t >> 6, c = t & 63;
    float acc = b2[c];
#pragma unroll
    for (int k = 0; k < 16; k++)
        acc = fmaf(as[r * 16 + k], ws[k * 64 + c], acc);
    out[(r0 + r) * OUTC + c] = acc;
}

extern "C" void kernel_launch(void* const* d_in, const int* in_sizes, int n_in,
                              void* d_out, int out_size) {
    const float* x   = (const float*)d_in[0];
    const int*   ei  = (const int*)d_in[1];   // JAX silently downcast int64->int32
    const float* W1  = (const float*)d_in[2];
    const float* b1  = (const float*)d_in[3];
    const float* W2  = (const float*)d_in[4];
    const float* b2  = (const float*)d_in[5];
    float*       out = (float*)d_out;

    int E = in_sizes[1] / 2;
    const int* row = ei;       // sources
    const int* col = ei + E;   // targets

    float4* p_h;   cudaGetSymbolAddress((void**)&p_h,   g_h);
    float4* p_h2;  cudaGetSymbolAddress((void**)&p_h2,  g_h2);
    float4* p_agg; cudaGetSymbolAddress((void**)&p_agg, g_agg);

    k_init_deg<<<(NN + 255) / 256, 256>>>();
    k_count<<<(E / 4 + 255) / 256, 256>>>(col, E);
    k_dinv_blocksum<<<NBLK, 1024>>>();
    k_bscan<<<1, 128>>>();
    k_off<<<NBLK, 1024>>>();
    k_scatter<<<(E + 255) / 256, 256>>>(row, col, E);
    k_gemm1<<<NN / 16, 256>>>(x, W1);
    k_pullw<true><<<(NN * 32 + 255) / 256, 256>>>(p_h, p_h2, b1);
    k_pullw<false><<<(NN * 32 + 255) / 256, 256>>>(p_h2, p_agg, b1);
    k_gemm2<<<NN / 4, 256>>>(W2, b2, out);
}